// round 12
// baseline (speedup 1.0000x reference)
#include <cuda_runtime.h>
#include <cuda_bf16.h>
#include <math.h>

#define BB 32
#define NN 8192
#define DD 256
#define HH 8
#define NSEG 32          // segments per batch (256 tokens each)

typedef unsigned long long u64t;

// ------------------------- device scratch -------------------------
__device__ __align__(16) float g_Ws[HH * DD];               // prescaled by log2(e)
__device__ float g_c[HH];                                    // prescaled by log2(e)
__device__ __align__(16) float g_qh[DD];
__device__ __align__(16) float g_tpart[BB * NSEG * HH * DD]; // 8 MB
__device__ float g_zpart[BB * NSEG * HH];
__device__ __align__(16) float g_ctx[BB * DD];
__device__ __align__(16) float g_ao[BB * DD];
__device__ __align__(16) float g_pl[BB * DD];
__device__ __align__(16) float g_hid[BB * 4 * DD];
__device__ __align__(16) float g_res[BB * DD];
__device__ int g_mask_mode;

// ------------------------- f32x2 helpers -------------------------
__device__ __forceinline__ u64t pk(float lo, float hi) {
    u64t r; asm("mov.b64 %0,{%1,%2};" : "=l"(r) : "f"(lo), "f"(hi)); return r;
}
__device__ __forceinline__ void upk(u64t v, float& lo, float& hi) {
    asm("mov.b64 {%0,%1},%2;" : "=f"(lo), "=f"(hi) : "l"(v));
}
__device__ __forceinline__ u64t fma2(u64t a, u64t b, u64t c) {
    u64t d; asm("fma.rn.f32x2 %0,%1,%2,%3;" : "=l"(d) : "l"(a), "l"(b), "l"(c)); return d;
}
__device__ __forceinline__ u64t mul2(u64t a, u64t b) {
    u64t d; asm("mul.rn.f32x2 %0,%1,%2;" : "=l"(d) : "l"(a), "l"(b)); return d;
}
__device__ __forceinline__ u64t add2(u64t a, u64t b) {
    u64t d; asm("add.rn.f32x2 %0,%1,%2;" : "=l"(d) : "l"(a), "l"(b)); return d;
}
__device__ __forceinline__ float ex2f(float x) {
    float r; asm("ex2.approx.ftz.f32 %0,%1;" : "=f"(r) : "f"(x)); return r;
}
__device__ __forceinline__ u64t shfl64x(u64t v, int m) {
    return __shfl_xor_sync(0xffffffffu, v, m);
}

// ------------------------- mask handling -------------------------
__device__ __forceinline__ float load_maskv(const void* mask, int mode, size_t idx) {
    if (mode == 0) return ((const unsigned char*)mask)[idx] ? 1.0f : 0.0f;
    if (mode == 1) return ((const int*)mask)[idx] ? 1.0f : 0.0f;
    return ((const float*)mask)[idx];
}

// ------------------------- warp dot helpers -------------------------
__device__ __forceinline__ float wdot256(const float* __restrict__ W,
                                         const float* __restrict__ x, int lane) {
    float4 w0 = *(const float4*)(W + 4 * lane);
    float4 w1 = *(const float4*)(W + 128 + 4 * lane);
    float4 x0 = *(const float4*)(x + 4 * lane);
    float4 x1 = *(const float4*)(x + 128 + 4 * lane);
    float s = w0.x * x0.x + w0.y * x0.y + w0.z * x0.z + w0.w * x0.w
            + w1.x * x1.x + w1.y * x1.y + w1.z * x1.z + w1.w * x1.w;
    #pragma unroll
    for (int m = 16; m; m >>= 1) s += __shfl_xor_sync(0xffffffffu, s, m);
    return s;
}

// ------------------------- prep: qh (+ mask detect in block 0) -------------------------
__global__ void prep_qh_kernel(const float* __restrict__ query, const float* __restrict__ Wq,
                               const float* __restrict__ bq, const unsigned* __restrict__ mask) {
    if (blockIdx.x == 0) {
        __shared__ int sF, sBig;
        const int tid = threadIdx.x;
        if (tid == 0) { sF = 0; sBig = 0; }
        __syncthreads();
        int f = 0, big = 0;
        for (int i = tid; i < 4096; i += blockDim.x) {
            unsigned x = mask[i];
            if (x == 0x3F800000u) f++;
            else if (x > 1u) big++;
        }
        atomicAdd(&sF, f); atomicAdd(&sBig, big);
        __syncthreads();
        if (tid == 0)
            g_mask_mode = (sF > 1000) ? 2 : ((sBig > 100) ? 0 : 1);
    }
    const int lane = threadIdx.x & 31;
    const int j = blockIdx.x * 8 + (threadIdx.x >> 5);
    float v = bq[j] + wdot256(Wq + (size_t)j * DD, query, lane);
    if (lane == 0) g_qh[j] = v * 0.17677669529663687f; // 1/sqrt(32)
}

// one block per head
__global__ void prep_ws_kernel(const float* __restrict__ Wk, const float* __restrict__ bk) {
    const int h = blockIdx.x, t = threadIdx.x;
    __shared__ float q[32];
    if (t < 32) q[t] = g_qh[h * 32 + t];
    __syncthreads();
    const float LOG2E = 1.4426950408889634f;
    float s = 0.f;
    #pragma unroll
    for (int dh = 0; dh < 32; dh++)
        s += q[dh] * Wk[(size_t)(h * 32 + dh) * DD + t];
    g_Ws[h * DD + t] = s * LOG2E;
    if (t == 0) {
        float c = 0.f;
        #pragma unroll
        for (int dh = 0; dh < 32; dh++) c += q[dh] * bk[h * 32 + dh];
        g_c[h] = c * LOG2E;
    }
}

// ------------------------- main fused attention pass (round-7 structure, NSEG=32) ----------
// Grid (32 seg, 32 batch), 128 threads = 4 warps = 2 stream-pairs.
// Pair p = w>>1 owns 128 contiguous tokens; warp parity hh = w&1 owns heads hh*4..hh*4+3.
// Group of 4 tokens. Loads for group g+1 are issued into the dead v-registers right
// after v(g) is re-paired into tk(g), BEFORE the butterfly/exp/accum math.
__global__ void __launch_bounds__(128, 3) attn_main_kernel(const float* __restrict__ tokens,
                                                           const void* __restrict__ mask) {
    const int s = blockIdx.x, b = blockIdx.y;
    const int tid = threadIdx.x, w = tid >> 5, lane = tid & 31;
    const int p = w >> 1, hh = w & 1;

    __shared__ __align__(16) u64t sred[HH * 128];   // 8 KB tail buffer
    __shared__ float szbf[16];

    // Ws for my 4 heads, as f32x2 pairs
    u64t Ws2[4][4];
    #pragma unroll
    for (int hc = 0; hc < 4; hc++) {
        const int h = hh * 4 + hc;
        float4 a = *(const float4*)(g_Ws + h * DD + 4 * lane);
        float4 c = *(const float4*)(g_Ws + h * DD + 128 + 4 * lane);
        Ws2[hc][0] = pk(a.x, a.y);  Ws2[hc][1] = pk(a.z, a.w);
        Ws2[hc][2] = pk(c.x, c.y);  Ws2[hc][3] = pk(c.z, c.w);
    }
    const u64t cp0 = pk(g_c[hh * 4 + 0], g_c[hh * 4 + 1]);
    const u64t cp1 = pk(g_c[hh * 4 + 2], g_c[hh * 4 + 3]);

    u64t acc2[4][4];
    #pragma unroll
    for (int hc = 0; hc < 4; hc++)
        #pragma unroll
        for (int j = 0; j < 4; j++) acc2[hc][j] = 0ull;
    u64t zacc0 = 0ull, zacc1 = 0ull;

    const int mode = g_mask_mode;
    const size_t rowbase = (size_t)b * NN + (size_t)s * 256 + (size_t)p * 128;
    const float4* tokp = (const float4*)tokens;

    // preload group 0 (4 tokens)
    float4 v[4][2]; float cmv[4];
    #pragma unroll
    for (int it = 0; it < 4; it++) {
        const size_t r = rowbase + it;
        v[it][0] = tokp[r * 64 + lane];
        v[it][1] = tokp[r * 64 + 32 + lane];
        cmv[it] = load_maskv(mask, mode, r);
    }

    #pragma unroll 1
    for (int g = 0; g < 32; g++) {
        // re-pair current group into tk (register aliasing, no data movement)
        u64t tk[4][4];
        float mv[4];
        #pragma unroll
        for (int it = 0; it < 4; it++) {
            tk[it][0] = pk(v[it][0].x, v[it][0].y);
            tk[it][1] = pk(v[it][0].z, v[it][0].w);
            tk[it][2] = pk(v[it][1].x, v[it][1].y);
            tk[it][3] = pk(v[it][1].z, v[it][1].w);
            mv[it] = cmv[it];
        }

        // immediately issue next group's loads into the dead v registers
        if (g < 31) {
            #pragma unroll
            for (int it = 0; it < 4; it++) {
                const size_t r = rowbase + 4 * (g + 1) + it;
                v[it][0] = tokp[r * 64 + lane];
                v[it][1] = tokp[r * 64 + 32 + lane];
                cmv[it] = load_maskv(mask, mode, r);
            }
        }

        // per-lane partial scores for my 4 heads, packed as head-pairs
        u64t bf[8];
        #pragma unroll
        for (int it = 0; it < 4; it++) {
            float sh[4];
            #pragma unroll
            for (int hc = 0; hc < 4; hc++) {
                u64t pp = mul2(tk[it][0], Ws2[hc][0]);
                pp = fma2(tk[it][1], Ws2[hc][1], pp);
                pp = fma2(tk[it][2], Ws2[hc][2], pp);
                pp = fma2(tk[it][3], Ws2[hc][3], pp);
                float lo, hi; upk(pp, lo, hi);
                sh[hc] = lo + hi;
            }
            bf[2 * it]     = pk(sh[0], sh[1]);
            bf[2 * it + 1] = pk(sh[2], sh[3]);
        }

        // butterfly: 8 independent chains, 5 levels
        #pragma unroll
        for (int m = 1; m <= 16; m <<= 1) {
            #pragma unroll
            for (int k = 0; k < 8; k++) bf[k] = add2(bf[k], shfl64x(bf[k], m));
        }

        // bias + exp2 + mask + z + accumulate
        #pragma unroll
        for (int it = 0; it < 4; it++) {
            const u64t s0 = add2(bf[2 * it], cp0);
            const u64t s1 = add2(bf[2 * it + 1], cp1);
            float a0, a1, a2, a3;
            upk(s0, a0, a1); upk(s1, a2, a3);
            const float m4 = mv[it];
            const float e0 = ex2f(a0) * m4, e1 = ex2f(a1) * m4;
            const float e2 = ex2f(a2) * m4, e3 = ex2f(a3) * m4;
            zacc0 = add2(zacc0, pk(e0, e1));
            zacc1 = add2(zacc1, pk(e2, e3));
            const u64t eb0 = pk(e0, e0), eb1 = pk(e1, e1);
            const u64t eb2 = pk(e2, e2), eb3 = pk(e3, e3);
            #pragma unroll
            for (int j = 0; j < 4; j++) {
                acc2[0][j] = fma2(tk[it][j], eb0, acc2[0][j]);
                acc2[1][j] = fma2(tk[it][j], eb1, acc2[1][j]);
                acc2[2][j] = fma2(tk[it][j], eb2, acc2[2][j]);
                acc2[3][j] = fma2(tk[it][j], eb3, acc2[3][j]);
            }
        }
    }

    // ---- tail: combine the two stream-pairs ----
    #pragma unroll
    for (int phase = 0; phase < 2; phase++) {
        if (p == phase) {
            #pragma unroll
            for (int hc = 0; hc < 4; hc++) {
                #pragma unroll
                for (int j = 0; j < 4; j++) {
                    const int pairpos = (j < 2) ? (2 * lane + j) : (64 + 2 * lane + (j - 2));
                    const int idx = (hh * 4 + hc) * 128 + pairpos;
                    if (phase == 0) sred[idx] = acc2[hc][j];
                    else            sred[idx] = add2(sred[idx], acc2[hc][j]);
                }
            }
            if (lane == 0) {
                float z0, z1, z2, z3;
                upk(zacc0, z0, z1); upk(zacc1, z2, z3);
                szbf[w * 4 + 0] = z0; szbf[w * 4 + 1] = z1;
                szbf[w * 4 + 2] = z2; szbf[w * 4 + 3] = z3;
            }
        }
        __syncthreads();
    }

    const int part = b * NSEG + s;
    u64t* tpart2 = (u64t*)g_tpart;
    #pragma unroll
    for (int k = 0; k < 4; k++) {
        tpart2[(size_t)part * 1024 + k * 256 + tid]       = sred[k * 256 + tid];
        tpart2[(size_t)part * 1024 + k * 256 + 128 + tid] = sred[k * 256 + 128 + tid];
    }
    if (tid < 8) {
        const int hhb = tid >> 2, j = tid & 3;
        g_zpart[part * 8 + tid] = szbf[hhb * 4 + j] + szbf[8 + hhb * 4 + j];
    }
}

// ------------------------- fused ctx kernel: z + segment-reduce + Wv dots -------------------------
// Grid 256 = (batch, head); block 256 threads.
// Reduction: thread (r = tid>>6, q = tid&63) sums 8 independent float4 loads
// (segments r, r+4, ..., r+28), 4-way smem combine — high MLP, near DRAM roofline.
__global__ void __launch_bounds__(256) ep_ctx_kernel(const float* __restrict__ Wv,
                                                     const float* __restrict__ bv) {
    const int b = blockIdx.x >> 3, h = blockIdx.x & 7;
    const int t = threadIdx.x, w = t >> 5, lane = t & 31;
    const int q = t & 63, r = t >> 6;
    __shared__ float4 sac[4][64];
    __shared__ float tbn[DD];
    __shared__ float szp[NSEG];
    __shared__ float zinv;

    const float4* base = (const float4*)(g_tpart) + (size_t)(b * NSEG) * 512 + h * 64;
    float4 acc = make_float4(0.f, 0.f, 0.f, 0.f);
    #pragma unroll
    for (int k = 0; k < 8; k++) {
        const float4 vv = base[(size_t)(r + 4 * k) * 512 + q];
        acc.x += vv.x; acc.y += vv.y; acc.z += vv.z; acc.w += vv.w;
    }
    sac[r][q] = acc;
    if (t < NSEG) szp[t] = g_zpart[(b * NSEG + t) * HH + h];
    __syncthreads();
    if (t == 0) {
        float z = 0.f;
        #pragma unroll
        for (int i = 0; i < NSEG; i++) z += szp[i];
        zinv = 1.0f / z;
    }
    __syncthreads();
    if (r == 0) {
        const float4 a0 = sac[0][q], a1 = sac[1][q], a2 = sac[2][q], a3 = sac[3][q];
        float4 sv;
        sv.x = ((a0.x + a1.x) + (a2.x + a3.x)) * zinv;
        sv.y = ((a0.y + a1.y) + (a2.y + a3.y)) * zinv;
        sv.z = ((a0.z + a1.z) + (a2.z + a3.z)) * zinv;
        sv.w = ((a0.w + a1.w) + (a2.w + a3.w)) * zinv;
        *(float4*)(tbn + 4 * q) = sv;
    }
    __syncthreads();

    #pragma unroll
    for (int o = 0; o < 4; o++) {
        const int j = h * 32 + w * 4 + o;
        float v = bv[j] + wdot256(Wv + (size_t)j * DD, tbn, lane);
        if (lane == 0) g_ctx[b * DD + j] = v;
    }
}

// ------------------------- epilogue -------------------------
__global__ void ep_attnout_kernel(const float* __restrict__ Wo, const float* __restrict__ bo) {
    const int lane = threadIdx.x & 31;
    const int gw = blockIdx.x * 8 + (threadIdx.x >> 5);
    const int b = gw & 31, t = gw >> 5;
    float v = bo[t] + wdot256(Wo + (size_t)t * DD, g_ctx + (size_t)b * DD, lane);
    if (lane == 0) g_ao[b * DD + t] = v;
}

__global__ void ep_ln1_kernel(const float* __restrict__ gg, const float* __restrict__ bb) {
    const int b = blockIdx.x, t = threadIdx.x, w = t >> 5, lane = t & 31;
    __shared__ u64t sw[8];
    const float v = g_ao[b * DD + t];
    u64t pr = pk(v, v * v);
    #pragma unroll
    for (int m = 16; m; m >>= 1) pr = add2(pr, shfl64x(pr, m));
    if (lane == 0) sw[w] = pr;
    __syncthreads();
    float s1 = 0.f, s2 = 0.f;
    #pragma unroll
    for (int i = 0; i < 8; i++) { float a, qq; upk(sw[i], a, qq); s1 += a; s2 += qq; }
    const float m = s1 * (1.0f / DD);
    const float var = s2 * (1.0f / DD) - m * m;
    g_pl[b * DD + t] = (v - m) * rsqrtf(var + 1e-5f) * gg[t] + bb[t];
}

// batched hidden GEMV: one warp per k-row computes ALL 32 batches (W1 read once).
__global__ void __launch_bounds__(256) ep_hidden_kernel(const float* __restrict__ W1,
                                                        const float* __restrict__ b1) {
    __shared__ float spl[BB * DD];
    const int tid = threadIdx.x, w = tid >> 5, lane = tid & 31;
    const int k = blockIdx.x * 8 + w;
    for (int i = tid; i < BB * DD; i += 256) spl[i] = g_pl[i];
    __syncthreads();
    const float4 w0 = *(const float4*)(W1 + (size_t)k * DD + 4 * lane);
    const float4 w1 = *(const float4*)(W1 + (size_t)k * DD + 128 + 4 * lane);
    float accv = 0.f;
    #pragma unroll
    for (int b = 0; b < BB; b++) {
        const float4 x0 = *(const float4*)(spl + b * DD + 4 * lane);
        const float4 x1 = *(const float4*)(spl + b * DD + 128 + 4 * lane);
        float s = w0.x * x0.x + w0.y * x0.y + w0.z * x0.z + w0.w * x0.w
                + w1.x * x1.x + w1.y * x1.y + w1.z * x1.z + w1.w * x1.w;
        #pragma unroll
        for (int m = 16; m; m >>= 1) s += __shfl_xor_sync(0xffffffffu, s, m);
        if (lane == b) accv = s;
    }
    const float hv = accv + b1[k];
    g_hid[(size_t)lane * 1024 + k] = 0.5f * hv * (1.0f + erff(hv * 0.70710678118654752f));
}

// batched mlp GEMV: warp per t-row, 8 batches per block, hid tiled through smem.
__global__ void __launch_bounds__(256) ep_mlp_kernel(const float* __restrict__ W2,
                                                     const float* __restrict__ b2) {
    __shared__ float shid[8 * DD];
    const int tid = threadIdx.x, w = tid >> 5, lane = tid & 31;
    const int t = (blockIdx.x >> 2) * 8 + w;
    const int b0 = (blockIdx.x & 3) * 8;
    float accv = 0.f;
    #pragma unroll 1
    for (int c = 0; c < 4; c++) {
        __syncthreads();
        for (int i = tid; i < 8 * DD; i += 256) {
            const int bl = i >> 8, d = i & 255;
            shid[i] = g_hid[(size_t)(b0 + bl) * 1024 + c * 256 + d];
        }
        __syncthreads();
        const float4 w0 = *(const float4*)(W2 + (size_t)t * 1024 + c * 256 + 4 * lane);
        const float4 w1 = *(const float4*)(W2 + (size_t)t * 1024 + c * 256 + 128 + 4 * lane);
        #pragma unroll
        for (int bl = 0; bl < 8; bl++) {
            const float4 x0 = *(const float4*)(shid + bl * DD + 4 * lane);
            const float4 x1 = *(const float4*)(shid + bl * DD + 128 + 4 * lane);
            float s = w0.x * x0.x + w0.y * x0.y + w0.z * x0.z + w0.w * x0.w
                    + w1.x * x1.x + w1.y * x1.y + w1.z * x1.z + w1.w * x1.w;
            #pragma unroll
            for (int m = 16; m; m >>= 1) s += __shfl_xor_sync(0xffffffffu, s, m);
            if (lane == bl) accv += s;
        }
    }
    if (lane < 8) {
        const int b = b0 + lane;
        g_res[b * DD + t] = accv + b2[t] + g_pl[b * DD + t];
    }
}

__global__ void ep_ln2_kernel(const float* __restrict__ gg, const float* __restrict__ bb,
                              float* __restrict__ out) {
    const int b = blockIdx.x, t = threadIdx.x, w = t >> 5, lane = t & 31;
    __shared__ u64t sw[8];
    const float v = g_res[b * DD + t];
    u64t pr = pk(v, v * v);
    #pragma unroll
    for (int m = 16; m; m >>= 1) pr = add2(pr, shfl64x(pr, m));
    if (lane == 0) sw[w] = pr;
    __syncthreads();
    float s1 = 0.f, s2 = 0.f;
    #pragma unroll
    for (int i = 0; i < 8; i++) { float a, qq; upk(sw[i], a, qq); s1 += a; s2 += qq; }
    const float m = s1 * (1.0f / DD);
    const float var = s2 * (1.0f / DD) - m * m;
    out[b * DD + t] = (v - m) * rsqrtf(var + 1e-5f) * gg[t] + bb[t];
}

// ------------------------- launch -------------------------
extern "C" void kernel_launch(void* const* d_in, const int* in_sizes, int n_in,
                              void* d_out, int out_size) {
    const float* tokens = (const float*)d_in[0];
    const void*  mask   = d_in[1];
    const float* query  = (const float*)d_in[2];
    const float* Wq     = (const float*)d_in[3];
    const float* bq     = (const float*)d_in[4];
    const float* Wk     = (const float*)d_in[5];
    const float* bk     = (const float*)d_in[6];
    const float* Wv     = (const float*)d_in[7];
    const float* bv     = (const float*)d_in[8];
    const float* Wo     = (const float*)d_in[9];
    const float* bo     = (const float*)d_in[10];
    const float* ln1g   = (const float*)d_in[11];
    const float* ln1b   = (const float*)d_in[12];
    const float* W1     = (const float*)d_in[13];
    const float* b1     = (const float*)d_in[14];
    const float* W2     = (const float*)d_in[15];
    const float* b2     = (const float*)d_in[16];
    const float* ln2g   = (const float*)d_in[17];
    const float* ln2b   = (const float*)d_in[18];
    float* out = (float*)d_out;

    prep_qh_kernel<<<32, 256>>>(query, Wq, bq, (const unsigned*)mask);
    prep_ws_kernel<<<8, 256>>>(Wk, bk);
    attn_main_kernel<<<dim3(32, 32), 128>>>(tokens, mask);
    ep_ctx_kernel<<<256, 256>>>(Wv, bv);
    ep_attnout_kernel<<<1024, 256>>>(Wo, bo);
    ep_ln1_kernel<<<32, 256>>>(ln1g, ln1b);
    ep_hidden_kernel<<<128, 256>>>(W1, b1);
    ep_mlp_kernel<<<128, 256>>>(W2, b2);
    ep_ln2_kernel<<<32, 256>>>(ln2g, ln2b, out);
}

// round 13
// speedup vs baseline: 1.0304x; 1.0304x over previous
#include <cuda_runtime.h>
#include <cuda_bf16.h>
#include <math.h>

#define BB 32
#define NN 8192
#define DD 256
#define HH 8
#define NSEG 64          // segments per batch (128 tokens each)

typedef unsigned long long u64t;

// ------------------------- device scratch -------------------------
__device__ __align__(16) float g_Ws[HH * DD];               // prescaled by log2(e)
__device__ float g_c[HH];                                    // prescaled by log2(e)
__device__ __align__(16) float g_qh[DD];
__device__ __align__(16) float g_tpart[BB * NSEG * HH * DD]; // 16 MB
__device__ float g_zpart[BB * NSEG * HH];
__device__ __align__(16) float g_ctx[BB * DD];
__device__ __align__(16) float g_ao[BB * DD];
__device__ __align__(16) float g_pl[BB * DD];
__device__ __align__(16) float g_hid[BB * 4 * DD];
__device__ __align__(16) float g_res[BB * DD];
__device__ int g_mask_mode;

// ------------------------- f32x2 helpers -------------------------
__device__ __forceinline__ u64t pk(float lo, float hi) {
    u64t r; asm("mov.b64 %0,{%1,%2};" : "=l"(r) : "f"(lo), "f"(hi)); return r;
}
__device__ __forceinline__ void upk(u64t v, float& lo, float& hi) {
    asm("mov.b64 {%0,%1},%2;" : "=f"(lo), "=f"(hi) : "l"(v));
}
__device__ __forceinline__ u64t fma2(u64t a, u64t b, u64t c) {
    u64t d; asm("fma.rn.f32x2 %0,%1,%2,%3;" : "=l"(d) : "l"(a), "l"(b), "l"(c)); return d;
}
__device__ __forceinline__ u64t mul2(u64t a, u64t b) {
    u64t d; asm("mul.rn.f32x2 %0,%1,%2;" : "=l"(d) : "l"(a), "l"(b)); return d;
}
__device__ __forceinline__ u64t add2(u64t a, u64t b) {
    u64t d; asm("add.rn.f32x2 %0,%1,%2;" : "=l"(d) : "l"(a), "l"(b)); return d;
}
__device__ __forceinline__ float ex2f(float x) {
    float r; asm("ex2.approx.ftz.f32 %0,%1;" : "=f"(r) : "f"(x)); return r;
}
__device__ __forceinline__ u64t shfl64x(u64t v, int m) {
    return __shfl_xor_sync(0xffffffffu, v, m);
}

// ------------------------- mask handling -------------------------
__device__ __forceinline__ float load_maskv(const void* mask, int mode, size_t idx) {
    if (mode == 0) return ((const unsigned char*)mask)[idx] ? 1.0f : 0.0f;
    if (mode == 1) return ((const int*)mask)[idx] ? 1.0f : 0.0f;
    return ((const float*)mask)[idx];
}

// ------------------------- warp dot helpers -------------------------
__device__ __forceinline__ float wdot256(const float* __restrict__ W,
                                         const float* __restrict__ x, int lane) {
    float4 w0 = *(const float4*)(W + 4 * lane);
    float4 w1 = *(const float4*)(W + 128 + 4 * lane);
    float4 x0 = *(const float4*)(x + 4 * lane);
    float4 x1 = *(const float4*)(x + 128 + 4 * lane);
    float s = w0.x * x0.x + w0.y * x0.y + w0.z * x0.z + w0.w * x0.w
            + w1.x * x1.x + w1.y * x1.y + w1.z * x1.z + w1.w * x1.w;
    #pragma unroll
    for (int m = 16; m; m >>= 1) s += __shfl_xor_sync(0xffffffffu, s, m);
    return s;
}

// ------------------------- prep: qh (+ mask detect in block 0) -------------------------
__global__ void prep_qh_kernel(const float* __restrict__ query, const float* __restrict__ Wq,
                               const float* __restrict__ bq, const unsigned* __restrict__ mask) {
    if (blockIdx.x == 0) {
        __shared__ int sF, sBig;
        const int tid = threadIdx.x;
        if (tid == 0) { sF = 0; sBig = 0; }
        __syncthreads();
        int f = 0, big = 0;
        for (int i = tid; i < 4096; i += blockDim.x) {
            unsigned x = mask[i];
            if (x == 0x3F800000u) f++;
            else if (x > 1u) big++;
        }
        atomicAdd(&sF, f); atomicAdd(&sBig, big);
        __syncthreads();
        if (tid == 0)
            g_mask_mode = (sF > 1000) ? 2 : ((sBig > 100) ? 0 : 1);
    }
    const int lane = threadIdx.x & 31;
    const int j = blockIdx.x * 8 + (threadIdx.x >> 5);
    float v = bq[j] + wdot256(Wq + (size_t)j * DD, query, lane);
    if (lane == 0) g_qh[j] = v * 0.17677669529663687f; // 1/sqrt(32)
}

// one block per head
__global__ void prep_ws_kernel(const float* __restrict__ Wk, const float* __restrict__ bk) {
    const int h = blockIdx.x, t = threadIdx.x;
    __shared__ float q[32];
    if (t < 32) q[t] = g_qh[h * 32 + t];
    __syncthreads();
    const float LOG2E = 1.4426950408889634f;
    float s = 0.f;
    #pragma unroll
    for (int dh = 0; dh < 32; dh++)
        s += q[dh] * Wk[(size_t)(h * 32 + dh) * DD + t];
    g_Ws[h * DD + t] = s * LOG2E;
    if (t == 0) {
        float c = 0.f;
        #pragma unroll
        for (int dh = 0; dh < 32; dh++) c += q[dh] * bk[h * 32 + dh];
        g_c[h] = c * LOG2E;
    }
}

// ------------------------- main fused attention pass (round-7/11 verbatim: best measured) ----------
// Grid (64 seg, 32 batch), 128 threads = 4 warps = 2 stream-pairs.
// Pair p = w>>1 owns 64 contiguous tokens; warp parity hh = w&1 owns heads hh*4..hh*4+3.
// Group of 4 tokens. Loads for group g+1 are issued into the dead v-registers right
// after v(g) is re-paired into tk(g), BEFORE the butterfly/exp/accum math.
__global__ void __launch_bounds__(128, 3) attn_main_kernel(const float* __restrict__ tokens,
                                                           const void* __restrict__ mask) {
    const int s = blockIdx.x, b = blockIdx.y;
    const int tid = threadIdx.x, w = tid >> 5, lane = tid & 31;
    const int p = w >> 1, hh = w & 1;

    __shared__ __align__(16) u64t sred[HH * 128];   // 8 KB tail buffer
    __shared__ float szbf[16];

    // Ws for my 4 heads, as f32x2 pairs
    u64t Ws2[4][4];
    #pragma unroll
    for (int hc = 0; hc < 4; hc++) {
        const int h = hh * 4 + hc;
        float4 a = *(const float4*)(g_Ws + h * DD + 4 * lane);
        float4 c = *(const float4*)(g_Ws + h * DD + 128 + 4 * lane);
        Ws2[hc][0] = pk(a.x, a.y);  Ws2[hc][1] = pk(a.z, a.w);
        Ws2[hc][2] = pk(c.x, c.y);  Ws2[hc][3] = pk(c.z, c.w);
    }
    const u64t cp0 = pk(g_c[hh * 4 + 0], g_c[hh * 4 + 1]);
    const u64t cp1 = pk(g_c[hh * 4 + 2], g_c[hh * 4 + 3]);

    u64t acc2[4][4];
    #pragma unroll
    for (int hc = 0; hc < 4; hc++)
        #pragma unroll
        for (int j = 0; j < 4; j++) acc2[hc][j] = 0ull;
    u64t zacc0 = 0ull, zacc1 = 0ull;

    const int mode = g_mask_mode;
    const size_t rowbase = (size_t)b * NN + (size_t)s * 128 + (size_t)p * 64;
    const float4* tokp = (const float4*)tokens;

    // preload group 0 (4 tokens)
    float4 v[4][2]; float cmv[4];
    #pragma unroll
    for (int it = 0; it < 4; it++) {
        const size_t r = rowbase + it;
        v[it][0] = tokp[r * 64 + lane];
        v[it][1] = tokp[r * 64 + 32 + lane];
        cmv[it] = load_maskv(mask, mode, r);
    }

    #pragma unroll 1
    for (int g = 0; g < 16; g++) {
        // re-pair current group into tk (register aliasing, no data movement)
        u64t tk[4][4];
        float mv[4];
        #pragma unroll
        for (int it = 0; it < 4; it++) {
            tk[it][0] = pk(v[it][0].x, v[it][0].y);
            tk[it][1] = pk(v[it][0].z, v[it][0].w);
            tk[it][2] = pk(v[it][1].x, v[it][1].y);
            tk[it][3] = pk(v[it][1].z, v[it][1].w);
            mv[it] = cmv[it];
        }

        // immediately issue next group's loads into the dead v registers
        if (g < 15) {
            #pragma unroll
            for (int it = 0; it < 4; it++) {
                const size_t r = rowbase + 4 * (g + 1) + it;
                v[it][0] = tokp[r * 64 + lane];
                v[it][1] = tokp[r * 64 + 32 + lane];
                cmv[it] = load_maskv(mask, mode, r);
            }
        }

        // per-lane partial scores for my 4 heads, packed as head-pairs
        u64t bf[8];
        #pragma unroll
        for (int it = 0; it < 4; it++) {
            float sh[4];
            #pragma unroll
            for (int hc = 0; hc < 4; hc++) {
                u64t pp = mul2(tk[it][0], Ws2[hc][0]);
                pp = fma2(tk[it][1], Ws2[hc][1], pp);
                pp = fma2(tk[it][2], Ws2[hc][2], pp);
                pp = fma2(tk[it][3], Ws2[hc][3], pp);
                float lo, hi; upk(pp, lo, hi);
                sh[hc] = lo + hi;
            }
            bf[2 * it]     = pk(sh[0], sh[1]);
            bf[2 * it + 1] = pk(sh[2], sh[3]);
        }

        // butterfly: 8 independent chains, 5 levels
        #pragma unroll
        for (int m = 1; m <= 16; m <<= 1) {
            #pragma unroll
            for (int k = 0; k < 8; k++) bf[k] = add2(bf[k], shfl64x(bf[k], m));
        }

        // bias + exp2 + mask + z + accumulate
        #pragma unroll
        for (int it = 0; it < 4; it++) {
            const u64t s0 = add2(bf[2 * it], cp0);
            const u64t s1 = add2(bf[2 * it + 1], cp1);
            float a0, a1, a2, a3;
            upk(s0, a0, a1); upk(s1, a2, a3);
            const float m4 = mv[it];
            const float e0 = ex2f(a0) * m4, e1 = ex2f(a1) * m4;
            const float e2 = ex2f(a2) * m4, e3 = ex2f(a3) * m4;
            zacc0 = add2(zacc0, pk(e0, e1));
            zacc1 = add2(zacc1, pk(e2, e3));
            const u64t eb0 = pk(e0, e0), eb1 = pk(e1, e1);
            const u64t eb2 = pk(e2, e2), eb3 = pk(e3, e3);
            #pragma unroll
            for (int j = 0; j < 4; j++) {
                acc2[0][j] = fma2(tk[it][j], eb0, acc2[0][j]);
                acc2[1][j] = fma2(tk[it][j], eb1, acc2[1][j]);
                acc2[2][j] = fma2(tk[it][j], eb2, acc2[2][j]);
                acc2[3][j] = fma2(tk[it][j], eb3, acc2[3][j]);
            }
        }
    }

    // ---- tail: combine the two stream-pairs ----
    #pragma unroll
    for (int phase = 0; phase < 2; phase++) {
        if (p == phase) {
            #pragma unroll
            for (int hc = 0; hc < 4; hc++) {
                #pragma unroll
                for (int j = 0; j < 4; j++) {
                    const int pairpos = (j < 2) ? (2 * lane + j) : (64 + 2 * lane + (j - 2));
                    const int idx = (hh * 4 + hc) * 128 + pairpos;
                    if (phase == 0) sred[idx] = acc2[hc][j];
                    else            sred[idx] = add2(sred[idx], acc2[hc][j]);
                }
            }
            if (lane == 0) {
                float z0, z1, z2, z3;
                upk(zacc0, z0, z1); upk(zacc1, z2, z3);
                szbf[w * 4 + 0] = z0; szbf[w * 4 + 1] = z1;
                szbf[w * 4 + 2] = z2; szbf[w * 4 + 3] = z3;
            }
        }
        __syncthreads();
    }

    const int part = b * NSEG + s;
    u64t* tpart2 = (u64t*)g_tpart;
    #pragma unroll
    for (int k = 0; k < 4; k++) {
        tpart2[(size_t)part * 1024 + k * 256 + tid]       = sred[k * 256 + tid];
        tpart2[(size_t)part * 1024 + k * 256 + 128 + tid] = sred[k * 256 + 128 + tid];
    }
    if (tid < 8) {
        const int hhb = tid >> 2, j = tid & 3;
        g_zpart[part * 8 + tid] = szbf[hhb * 4 + j] + szbf[8 + hhb * 4 + j];
    }
}

// ------------------------- fused ctx kernel: z + segment-reduce + Wv dots -------------------------
// Grid 256 = (batch, head); block 256 threads.
// Reduction: thread (r = tid>>6, q = tid&63) sums 16 independent float4 loads
// (segments r, r+4, ..., r+60), 4-way smem combine — high MLP.
__global__ void __launch_bounds__(256) ep_ctx_kernel(const float* __restrict__ Wv,
                                                     const float* __restrict__ bv) {
    const int b = blockIdx.x >> 3, h = blockIdx.x & 7;
    const int t = threadIdx.x, w = t >> 5, lane = t & 31;
    const int q = t & 63, r = t >> 6;
    __shared__ float4 sac[4][64];
    __shared__ float tbn[DD];
    __shared__ float szp[NSEG];
    __shared__ float zinv;

    const float4* base = (const float4*)(g_tpart) + (size_t)(b * NSEG) * 512 + h * 64;
    float4 acc = make_float4(0.f, 0.f, 0.f, 0.f);
    #pragma unroll
    for (int k = 0; k < 16; k++) {
        const float4 vv = base[(size_t)(r + 4 * k) * 512 + q];
        acc.x += vv.x; acc.y += vv.y; acc.z += vv.z; acc.w += vv.w;
    }
    sac[r][q] = acc;
    if (t < NSEG) szp[t] = g_zpart[(b * NSEG + t) * HH + h];
    __syncthreads();
    if (t == 0) {
        float z = 0.f;
        #pragma unroll
        for (int i = 0; i < NSEG; i++) z += szp[i];
        zinv = 1.0f / z;
    }
    __syncthreads();
    if (r == 0) {
        const float4 a0 = sac[0][q], a1 = sac[1][q], a2 = sac[2][q], a3 = sac[3][q];
        float4 sv;
        sv.x = ((a0.x + a1.x) + (a2.x + a3.x)) * zinv;
        sv.y = ((a0.y + a1.y) + (a2.y + a3.y)) * zinv;
        sv.z = ((a0.z + a1.z) + (a2.z + a3.z)) * zinv;
        sv.w = ((a0.w + a1.w) + (a2.w + a3.w)) * zinv;
        *(float4*)(tbn + 4 * q) = sv;
    }
    __syncthreads();

    #pragma unroll
    for (int o = 0; o < 4; o++) {
        const int j = h * 32 + w * 4 + o;
        float v = bv[j] + wdot256(Wv + (size_t)j * DD, tbn, lane);
        if (lane == 0) g_ctx[b * DD + j] = v;
    }
}

// ------------------------- epilogue -------------------------
__global__ void ep_attnout_kernel(const float* __restrict__ Wo, const float* __restrict__ bo) {
    const int lane = threadIdx.x & 31;
    const int gw = blockIdx.x * 8 + (threadIdx.x >> 5);
    const int b = gw & 31, t = gw >> 5;
    float v = bo[t] + wdot256(Wo + (size_t)t * DD, g_ctx + (size_t)b * DD, lane);
    if (lane == 0) g_ao[b * DD + t] = v;
}

__global__ void ep_ln1_kernel(const float* __restrict__ gg, const float* __restrict__ bb) {
    const int b = blockIdx.x, t = threadIdx.x, w = t >> 5, lane = t & 31;
    __shared__ u64t sw[8];
    const float v = g_ao[b * DD + t];
    u64t pr = pk(v, v * v);
    #pragma unroll
    for (int m = 16; m; m >>= 1) pr = add2(pr, shfl64x(pr, m));
    if (lane == 0) sw[w] = pr;
    __syncthreads();
    float s1 = 0.f, s2 = 0.f;
    #pragma unroll
    for (int i = 0; i < 8; i++) { float a, qq; upk(sw[i], a, qq); s1 += a; s2 += qq; }
    const float m = s1 * (1.0f / DD);
    const float var = s2 * (1.0f / DD) - m * m;
    g_pl[b * DD + t] = (v - m) * rsqrtf(var + 1e-5f) * gg[t] + bb[t];
}

// batched hidden GEMV: one warp per k-row computes ALL 32 batches (W1 read once).
__global__ void __launch_bounds__(256) ep_hidden_kernel(const float* __restrict__ W1,
                                                        const float* __restrict__ b1) {
    __shared__ float spl[BB * DD];
    const int tid = threadIdx.x, w = tid >> 5, lane = tid & 31;
    const int k = blockIdx.x * 8 + w;
    for (int i = tid; i < BB * DD; i += 256) spl[i] = g_pl[i];
    __syncthreads();
    const float4 w0 = *(const float4*)(W1 + (size_t)k * DD + 4 * lane);
    const float4 w1 = *(const float4*)(W1 + (size_t)k * DD + 128 + 4 * lane);
    float accv = 0.f;
    #pragma unroll
    for (int b = 0; b < BB; b++) {
        const float4 x0 = *(const float4*)(spl + b * DD + 4 * lane);
        const float4 x1 = *(const float4*)(spl + b * DD + 128 + 4 * lane);
        float s = w0.x * x0.x + w0.y * x0.y + w0.z * x0.z + w0.w * x0.w
                + w1.x * x1.x + w1.y * x1.y + w1.z * x1.z + w1.w * x1.w;
        #pragma unroll
        for (int m = 16; m; m >>= 1) s += __shfl_xor_sync(0xffffffffu, s, m);
        if (lane == b) accv = s;
    }
    const float hv = accv + b1[k];
    g_hid[(size_t)lane * 1024 + k] = 0.5f * hv * (1.0f + erff(hv * 0.70710678118654752f));
}

// batched mlp GEMV: warp per t-row, 8 batches per block, hid tiled through smem.
__global__ void __launch_bounds__(256) ep_mlp_kernel(const float* __restrict__ W2,
                                                     const float* __restrict__ b2) {
    __shared__ float shid[8 * DD];
    const int tid = threadIdx.x, w = tid >> 5, lane = tid & 31;
    const int t = (blockIdx.x >> 2) * 8 + w;
    const int b0 = (blockIdx.x & 3) * 8;
    float accv = 0.f;
    #pragma unroll 1
    for (int c = 0; c < 4; c++) {
        __syncthreads();
        for (int i = tid; i < 8 * DD; i += 256) {
            const int bl = i >> 8, d = i & 255;
            shid[i] = g_hid[(size_t)(b0 + bl) * 1024 + c * 256 + d];
        }
        __syncthreads();
        const float4 w0 = *(const float4*)(W2 + (size_t)t * 1024 + c * 256 + 4 * lane);
        const float4 w1 = *(const float4*)(W2 + (size_t)t * 1024 + c * 256 + 128 + 4 * lane);
        #pragma unroll
        for (int bl = 0; bl < 8; bl++) {
            const float4 x0 = *(const float4*)(shid + bl * DD + 4 * lane);
            const float4 x1 = *(const float4*)(shid + bl * DD + 128 + 4 * lane);
            float s = w0.x * x0.x + w0.y * x0.y + w0.z * x0.z + w0.w * x0.w
                    + w1.x * x1.x + w1.y * x1.y + w1.z * x1.z + w1.w * x1.w;
            #pragma unroll
            for (int m = 16; m; m >>= 1) s += __shfl_xor_sync(0xffffffffu, s, m);
            if (lane == bl) accv += s;
        }
    }
    if (lane < 8) {
        const int b = b0 + lane;
        g_res[b * DD + t] = accv + b2[t] + g_pl[b * DD + t];
    }
}

__global__ void ep_ln2_kernel(const float* __restrict__ gg, const float* __restrict__ bb,
                              float* __restrict__ out) {
    const int b = blockIdx.x, t = threadIdx.x, w = t >> 5, lane = t & 31;
    __shared__ u64t sw[8];
    const float v = g_res[b * DD + t];
    u64t pr = pk(v, v * v);
    #pragma unroll
    for (int m = 16; m; m >>= 1) pr = add2(pr, shfl64x(pr, m));
    if (lane == 0) sw[w] = pr;
    __syncthreads();
    float s1 = 0.f, s2 = 0.f;
    #pragma unroll
    for (int i = 0; i < 8; i++) { float a, qq; upk(sw[i], a, qq); s1 += a; s2 += qq; }
    const float m = s1 * (1.0f / DD);
    const float var = s2 * (1.0f / DD) - m * m;
    out[b * DD + t] = (v - m) * rsqrtf(var + 1e-5f) * gg[t] + bb[t];
}

// ------------------------- launch -------------------------
extern "C" void kernel_launch(void* const* d_in, const int* in_sizes, int n_in,
                              void* d_out, int out_size) {
    const float* tokens = (const float*)d_in[0];
    const void*  mask   = d_in[1];
    const float* query  = (const float*)d_in[2];
    const float* Wq     = (const float*)d_in[3];
    const float* bq     = (const float*)d_in[4];
    const float* Wk     = (const float*)d_in[5];
    const float* bk     = (const float*)d_in[6];
    const float* Wv     = (const float*)d_in[7];
    const float* bv     = (const float*)d_in[8];
    const float* Wo     = (const float*)d_in[9];
    const float* bo     = (const float*)d_in[10];
    const float* ln1g   = (const float*)d_in[11];
    const float* ln1b   = (const float*)d_in[12];
    const float* W1     = (const float*)d_in[13];
    const float* b1     = (const float*)d_in[14];
    const float* W2     = (const float*)d_in[15];
    const float* b2     = (const float*)d_in[16];
    const float* ln2g   = (const float*)d_in[17];
    const float* ln2b   = (const float*)d_in[18];
    float* out = (float*)d_out;

    prep_qh_kernel<<<32, 256>>>(query, Wq, bq, (const unsigned*)mask);
    prep_ws_kernel<<<8, 256>>>(Wk, bk);
    attn_main_kernel<<<dim3(64, 32), 128>>>(tokens, mask);
    ep_ctx_kernel<<<256, 256>>>(Wv, bv);
    ep_attnout_kernel<<<1024, 256>>>(Wo, bo);
    ep_ln1_kernel<<<32, 256>>>(ln1g, ln1b);
    ep_hidden_kernel<<<128, 256>>>(W1, b1);
    ep_mlp_kernel<<<128, 256>>>(W2, b2);
    ep_ln2_kernel<<<32, 256>>>(ln2g, ln2b, out);
}

// round 14
// speedup vs baseline: 1.1763x; 1.1416x over previous
#include <cuda_runtime.h>
#include <cuda_bf16.h>
#include <math.h>

#define BB 32
#define NN 8192
#define DD 256
#define HH 8
#define NSEG 64            // segments per batch (128 tokens each)
#define CHUNK_TOK 16
#define CHUNK_BYTES (CHUNK_TOK * DD * 4)   // 16 KB

typedef unsigned long long u64t;

// ------------------------- device scratch -------------------------
__device__ __align__(16) float g_Ws[HH * DD];               // prescaled by log2(e)
__device__ float g_c[HH];                                    // prescaled by log2(e)
__device__ __align__(16) float g_qh[DD];
__device__ __align__(16) float g_tpart[BB * NSEG * HH * DD]; // 16 MB
__device__ float g_zpart[BB * NSEG * HH];
__device__ __align__(16) float g_ctx[BB * DD];
__device__ __align__(16) float g_ao[BB * DD];
__device__ __align__(16) float g_pl[BB * DD];
__device__ __align__(16) float g_hid[BB * 4 * DD];
__device__ __align__(16) float g_res[BB * DD];
__device__ int g_mask_mode;

// ------------------------- f32x2 helpers -------------------------
__device__ __forceinline__ u64t pk(float lo, float hi) {
    u64t r; asm("mov.b64 %0,{%1,%2};" : "=l"(r) : "f"(lo), "f"(hi)); return r;
}
__device__ __forceinline__ void upk(u64t v, float& lo, float& hi) {
    asm("mov.b64 {%0,%1},%2;" : "=f"(lo), "=f"(hi) : "l"(v));
}
__device__ __forceinline__ u64t fma2(u64t a, u64t b, u64t c) {
    u64t d; asm("fma.rn.f32x2 %0,%1,%2,%3;" : "=l"(d) : "l"(a), "l"(b), "l"(c)); return d;
}
__device__ __forceinline__ u64t mul2(u64t a, u64t b) {
    u64t d; asm("mul.rn.f32x2 %0,%1,%2;" : "=l"(d) : "l"(a), "l"(b)); return d;
}
__device__ __forceinline__ u64t add2(u64t a, u64t b) {
    u64t d; asm("add.rn.f32x2 %0,%1,%2;" : "=l"(d) : "l"(a), "l"(b)); return d;
}
__device__ __forceinline__ float ex2f(float x) {
    float r; asm("ex2.approx.ftz.f32 %0,%1;" : "=f"(r) : "f"(x)); return r;
}
__device__ __forceinline__ u64t shfl64x(u64t v, int m) {
    return __shfl_xor_sync(0xffffffffu, v, m);
}

// ------------------------- mbarrier / bulk-async helpers -------------------------
__device__ __forceinline__ void mbar_init(unsigned mb, unsigned cnt) {
    asm volatile("mbarrier.init.shared.b64 [%0], %1;" :: "r"(mb), "r"(cnt) : "memory");
}
__device__ __forceinline__ void mbar_expect_tx(unsigned mb, unsigned bytes) {
    asm volatile("mbarrier.arrive.expect_tx.shared.b64 _, [%0], %1;" :: "r"(mb), "r"(bytes) : "memory");
}
__device__ __forceinline__ void bulk_cp(unsigned dst, const void* src, unsigned bytes, unsigned mb) {
    asm volatile("cp.async.bulk.shared::cta.global.mbarrier::complete_tx::bytes [%0], [%1], %2, [%3];"
                 :: "r"(dst), "l"(src), "r"(bytes), "r"(mb) : "memory");
}
__device__ __forceinline__ void mbar_wait(unsigned mb, unsigned par) {
    unsigned done;
    asm volatile("{\n\t.reg .pred p;\n\t"
                 "mbarrier.try_wait.parity.acquire.cta.shared::cta.b64 p, [%1], %2;\n\t"
                 "selp.b32 %0, 1, 0, p;\n\t}"
                 : "=r"(done) : "r"(mb), "r"(par) : "memory");
    while (!done) {
        asm volatile("{\n\t.reg .pred p;\n\t"
                     "mbarrier.try_wait.parity.acquire.cta.shared::cta.b64 p, [%1], %2, 0x989680;\n\t"
                     "selp.b32 %0, 1, 0, p;\n\t}"
                     : "=r"(done) : "r"(mb), "r"(par) : "memory");
    }
}

// ------------------------- mask handling -------------------------
__device__ __forceinline__ float load_maskv(const void* mask, int mode, size_t idx) {
    if (mode == 0) return ((const unsigned char*)mask)[idx] ? 1.0f : 0.0f;
    if (mode == 1) return ((const int*)mask)[idx] ? 1.0f : 0.0f;
    return ((const float*)mask)[idx];
}

// ------------------------- warp dot helpers -------------------------
__device__ __forceinline__ float wdot256(const float* __restrict__ W,
                                         const float* __restrict__ x, int lane) {
    float4 w0 = *(const float4*)(W + 4 * lane);
    float4 w1 = *(const float4*)(W + 128 + 4 * lane);
    float4 x0 = *(const float4*)(x + 4 * lane);
    float4 x1 = *(const float4*)(x + 128 + 4 * lane);
    float s = w0.x * x0.x + w0.y * x0.y + w0.z * x0.z + w0.w * x0.w
            + w1.x * x1.x + w1.y * x1.y + w1.z * x1.z + w1.w * x1.w;
    #pragma unroll
    for (int m = 16; m; m >>= 1) s += __shfl_xor_sync(0xffffffffu, s, m);
    return s;
}

// ------------------------- prep: qh (+ mask detect in block 0) -------------------------
__global__ void prep_qh_kernel(const float* __restrict__ query, const float* __restrict__ Wq,
                               const float* __restrict__ bq, const unsigned* __restrict__ mask) {
    if (blockIdx.x == 0) {
        __shared__ int sF, sBig;
        const int tid = threadIdx.x;
        if (tid == 0) { sF = 0; sBig = 0; }
        __syncthreads();
        int f = 0, big = 0;
        for (int i = tid; i < 4096; i += blockDim.x) {
            unsigned x = mask[i];
            if (x == 0x3F800000u) f++;
            else if (x > 1u) big++;
        }
        atomicAdd(&sF, f); atomicAdd(&sBig, big);
        __syncthreads();
        if (tid == 0)
            g_mask_mode = (sF > 1000) ? 2 : ((sBig > 100) ? 0 : 1);
    }
    const int lane = threadIdx.x & 31;
    const int j = blockIdx.x * 8 + (threadIdx.x >> 5);
    float v = bq[j] + wdot256(Wq + (size_t)j * DD, query, lane);
    if (lane == 0) g_qh[j] = v * 0.17677669529663687f; // 1/sqrt(32)
}

// one block per head
__global__ void prep_ws_kernel(const float* __restrict__ Wk, const float* __restrict__ bk) {
    const int h = blockIdx.x, t = threadIdx.x;
    __shared__ float q[32];
    if (t < 32) q[t] = g_qh[h * 32 + t];
    __syncthreads();
    const float LOG2E = 1.4426950408889634f;
    float s = 0.f;
    #pragma unroll
    for (int dh = 0; dh < 32; dh++)
        s += q[dh] * Wk[(size_t)(h * 32 + dh) * DD + t];
    g_Ws[h * DD + t] = s * LOG2E;
    if (t == 0) {
        float c = 0.f;
        #pragma unroll
        for (int dh = 0; dh < 32; dh++) c += q[dh] * bk[h * 32 + dh];
        g_c[h] = c * LOG2E;
    }
}

// ------------------------- main fused attention pass: bulk-async smem pipeline ----------
// Grid (64 seg, 32 batch), 128 threads = 4 warps. Pair p = w>>1 owns 8 tokens per chunk;
// warp parity hh = w&1 owns heads hh*4..hh*4+3. Tokens staged to smem by cp.async.bulk
// (double-buffered 16-token chunks); warps read via transient LDS (score pass + accum pass).
__global__ void __launch_bounds__(128, 4) attn_main_kernel(const float* __restrict__ tokens,
                                                           const void* __restrict__ mask) {
    const int s = blockIdx.x, b = blockIdx.y;
    const int tid = threadIdx.x, w = tid >> 5, lane = tid & 31;
    const int p = w >> 1, hh = w & 1;

    __shared__ __align__(16) float sbuf[2][CHUNK_TOK * DD];   // 32 KB double buffer
    __shared__ __align__(8) unsigned long long smbar[2];
    __shared__ float szbf[16];
    u64t* sred = (u64t*)&sbuf[0][0];   // tail reuse (8 KB inside buffer 0)

    const unsigned sbase = (unsigned)__cvta_generic_to_shared(&sbuf[0][0]);
    const unsigned mb0 = (unsigned)__cvta_generic_to_shared(&smbar[0]);
    const unsigned mb1 = mb0 + 8;

    if (tid == 0) {
        mbar_init(mb0, 1);
        mbar_init(mb1, 1);
        asm volatile("fence.proxy.async.shared::cta;" ::: "memory");
    }
    __syncthreads();

    // Ws for my 4 heads, as f32x2 pairs
    u64t Ws2[4][4];
    #pragma unroll
    for (int hc = 0; hc < 4; hc++) {
        const int h = hh * 4 + hc;
        float4 a = *(const float4*)(g_Ws + h * DD + 4 * lane);
        float4 c = *(const float4*)(g_Ws + h * DD + 128 + 4 * lane);
        Ws2[hc][0] = pk(a.x, a.y);  Ws2[hc][1] = pk(a.z, a.w);
        Ws2[hc][2] = pk(c.x, c.y);  Ws2[hc][3] = pk(c.z, c.w);
    }
    const u64t cp0 = pk(g_c[hh * 4 + 0], g_c[hh * 4 + 1]);
    const u64t cp1 = pk(g_c[hh * 4 + 2], g_c[hh * 4 + 3]);

    u64t acc2[4][4];
    #pragma unroll
    for (int hc = 0; hc < 4; hc++)
        #pragma unroll
        for (int j = 0; j < 4; j++) acc2[hc][j] = 0ull;
    u64t zacc0 = 0ull, zacc1 = 0ull;

    const int mode = g_mask_mode;
    const size_t blockbase = (size_t)b * NN + (size_t)s * 128;   // token index
    const float* gsrc = tokens + blockbase * DD;

    // issue chunk 0
    if (tid == 0) {
        mbar_expect_tx(mb0, CHUNK_BYTES);
        bulk_cp(sbase, gsrc, CHUNK_BYTES, mb0);
    }

    #pragma unroll 1
    for (int c = 0; c < 8; c++) {
        if (c > 0) __syncthreads();   // buffer (c+1)&1 free (chunk c-1 consumed)
        if (c < 7 && tid == 0) {
            const unsigned mb = ((c + 1) & 1) ? mb1 : mb0;
            mbar_expect_tx(mb, CHUNK_BYTES);
            bulk_cp(sbase + ((c + 1) & 1) * CHUNK_BYTES,
                    gsrc + (size_t)(c + 1) * CHUNK_TOK * DD, CHUNK_BYTES, mb);
        }
        mbar_wait((c & 1) ? mb1 : mb0, (c >> 1) & 1);

        const float* cbuf = &sbuf[c & 1][0];
        #pragma unroll
        for (int gg = 0; gg < 2; gg++) {
            const int t0 = p * 8 + gg * 4;   // smem token index within chunk

            // masks (uniform scalar loads, issued early)
            float mv[4];
            #pragma unroll
            for (int it = 0; it < 4; it++)
                mv[it] = load_maskv(mask, mode, blockbase + (size_t)c * CHUNK_TOK + t0 + it);

            // score pass: transient LDS per token
            u64t bf[8];
            #pragma unroll
            for (int it = 0; it < 4; it++) {
                const float* tp = cbuf + (t0 + it) * DD;
                const float4 v0 = *(const float4*)(tp + 4 * lane);
                const float4 v1 = *(const float4*)(tp + 128 + 4 * lane);
                const u64t t0k = pk(v0.x, v0.y), t1k = pk(v0.z, v0.w);
                const u64t t2k = pk(v1.x, v1.y), t3k = pk(v1.z, v1.w);
                float sh[4];
                #pragma unroll
                for (int hc = 0; hc < 4; hc++) {
                    u64t pp = mul2(t0k, Ws2[hc][0]);
                    pp = fma2(t1k, Ws2[hc][1], pp);
                    pp = fma2(t2k, Ws2[hc][2], pp);
                    pp = fma2(t3k, Ws2[hc][3], pp);
                    float lo, hi; upk(pp, lo, hi);
                    sh[hc] = lo + hi;
                }
                bf[2 * it]     = pk(sh[0], sh[1]);
                bf[2 * it + 1] = pk(sh[2], sh[3]);
            }

            // butterfly: 8 independent chains, 5 levels
            #pragma unroll
            for (int m = 1; m <= 16; m <<= 1) {
                #pragma unroll
                for (int k = 0; k < 8; k++) bf[k] = add2(bf[k], shfl64x(bf[k], m));
            }

            // bias + exp2 + mask + z + accum (tk reloaded transiently)
            #pragma unroll
            for (int it = 0; it < 4; it++) {
                const u64t s0 = add2(bf[2 * it], cp0);
                const u64t s1 = add2(bf[2 * it + 1], cp1);
                float a0, a1, a2, a3;
                upk(s0, a0, a1); upk(s1, a2, a3);
                const float m4 = mv[it];
                const float e0 = ex2f(a0) * m4, e1 = ex2f(a1) * m4;
                const float e2 = ex2f(a2) * m4, e3 = ex2f(a3) * m4;
                zacc0 = add2(zacc0, pk(e0, e1));
                zacc1 = add2(zacc1, pk(e2, e3));
                const u64t eb0 = pk(e0, e0), eb1 = pk(e1, e1);
                const u64t eb2 = pk(e2, e2), eb3 = pk(e3, e3);
                const float* tp = cbuf + (t0 + it) * DD;
                const float4 v0 = *(const float4*)(tp + 4 * lane);
                const float4 v1 = *(const float4*)(tp + 128 + 4 * lane);
                const u64t t0k = pk(v0.x, v0.y), t1k = pk(v0.z, v0.w);
                const u64t t2k = pk(v1.x, v1.y), t3k = pk(v1.z, v1.w);
                acc2[0][0] = fma2(t0k, eb0, acc2[0][0]);
                acc2[0][1] = fma2(t1k, eb0, acc2[0][1]);
                acc2[0][2] = fma2(t2k, eb0, acc2[0][2]);
                acc2[0][3] = fma2(t3k, eb0, acc2[0][3]);
                acc2[1][0] = fma2(t0k, eb1, acc2[1][0]);
                acc2[1][1] = fma2(t1k, eb1, acc2[1][1]);
                acc2[1][2] = fma2(t2k, eb1, acc2[1][2]);
                acc2[1][3] = fma2(t3k, eb1, acc2[1][3]);
                acc2[2][0] = fma2(t0k, eb2, acc2[2][0]);
                acc2[2][1] = fma2(t1k, eb2, acc2[2][1]);
                acc2[2][2] = fma2(t2k, eb2, acc2[2][2]);
                acc2[2][3] = fma2(t3k, eb2, acc2[2][3]);
                acc2[3][0] = fma2(t0k, eb3, acc2[3][0]);
                acc2[3][1] = fma2(t1k, eb3, acc2[3][1]);
                acc2[3][2] = fma2(t2k, eb3, acc2[3][2]);
                acc2[3][3] = fma2(t3k, eb3, acc2[3][3]);
            }
        }
    }

    __syncthreads();   // all chunks consumed; safe to reuse sbuf as sred

    // ---- tail: combine the two stream-pairs ----
    #pragma unroll
    for (int phase = 0; phase < 2; phase++) {
        if (p == phase) {
            #pragma unroll
            for (int hc = 0; hc < 4; hc++) {
                #pragma unroll
                for (int j = 0; j < 4; j++) {
                    const int pairpos = (j < 2) ? (2 * lane + j) : (64 + 2 * lane + (j - 2));
                    const int idx = (hh * 4 + hc) * 128 + pairpos;
                    if (phase == 0) sred[idx] = acc2[hc][j];
                    else            sred[idx] = add2(sred[idx], acc2[hc][j]);
                }
            }
            if (lane == 0) {
                float z0, z1, z2, z3;
                upk(zacc0, z0, z1); upk(zacc1, z2, z3);
                szbf[w * 4 + 0] = z0; szbf[w * 4 + 1] = z1;
                szbf[w * 4 + 2] = z2; szbf[w * 4 + 3] = z3;
            }
        }
        __syncthreads();
    }

    const int part = b * NSEG + s;
    u64t* tpart2 = (u64t*)g_tpart;
    #pragma unroll
    for (int k = 0; k < 4; k++) {
        tpart2[(size_t)part * 1024 + k * 256 + tid]       = sred[k * 256 + tid];
        tpart2[(size_t)part * 1024 + k * 256 + 128 + tid] = sred[k * 256 + 128 + tid];
    }
    if (tid < 8) {
        const int hhb = tid >> 2, j = tid & 3;
        g_zpart[part * 8 + tid] = szbf[hhb * 4 + j] + szbf[8 + hhb * 4 + j];
    }
}

// ------------------------- fused ctx kernel: z + segment-reduce + Wv dots -------------------------
__global__ void __launch_bounds__(256) ep_ctx_kernel(const float* __restrict__ Wv,
                                                     const float* __restrict__ bv) {
    const int b = blockIdx.x >> 3, h = blockIdx.x & 7;
    const int t = threadIdx.x, w = t >> 5, lane = t & 31;
    const int q = t & 63, r = t >> 6;
    __shared__ float4 sac[4][64];
    __shared__ float tbn[DD];
    __shared__ float szp[NSEG];
    __shared__ float zinv;

    const float4* base = (const float4*)(g_tpart) + (size_t)(b * NSEG) * 512 + h * 64;
    float4 acc = make_float4(0.f, 0.f, 0.f, 0.f);
    #pragma unroll
    for (int k = 0; k < 16; k++) {
        const float4 vv = base[(size_t)(r + 4 * k) * 512 + q];
        acc.x += vv.x; acc.y += vv.y; acc.z += vv.z; acc.w += vv.w;
    }
    sac[r][q] = acc;
    if (t < NSEG) szp[t] = g_zpart[(b * NSEG + t) * HH + h];
    __syncthreads();
    if (t == 0) {
        float z = 0.f;
        #pragma unroll
        for (int i = 0; i < NSEG; i++) z += szp[i];
        zinv = 1.0f / z;
    }
    __syncthreads();
    if (r == 0) {
        const float4 a0 = sac[0][q], a1 = sac[1][q], a2 = sac[2][q], a3 = sac[3][q];
        float4 sv;
        sv.x = ((a0.x + a1.x) + (a2.x + a3.x)) * zinv;
        sv.y = ((a0.y + a1.y) + (a2.y + a3.y)) * zinv;
        sv.z = ((a0.z + a1.z) + (a2.z + a3.z)) * zinv;
        sv.w = ((a0.w + a1.w) + (a2.w + a3.w)) * zinv;
        *(float4*)(tbn + 4 * q) = sv;
    }
    __syncthreads();

    #pragma unroll
    for (int o = 0; o < 4; o++) {
        const int j = h * 32 + w * 4 + o;
        float v = bv[j] + wdot256(Wv + (size_t)j * DD, tbn, lane);
        if (lane == 0) g_ctx[b * DD + j] = v;
    }
}

// ------------------------- epilogue -------------------------
__global__ void ep_attnout_kernel(const float* __restrict__ Wo, const float* __restrict__ bo) {
    const int lane = threadIdx.x & 31;
    const int gw = blockIdx.x * 8 + (threadIdx.x >> 5);
    const int b = gw & 31, t = gw >> 5;
    float v = bo[t] + wdot256(Wo + (size_t)t * DD, g_ctx + (size_t)b * DD, lane);
    if (lane == 0) g_ao[b * DD + t] = v;
}

__global__ void ep_ln1_kernel(const float* __restrict__ gg, const float* __restrict__ bb) {
    const int b = blockIdx.x, t = threadIdx.x, w = t >> 5, lane = t & 31;
    __shared__ u64t sw[8];
    const float v = g_ao[b * DD + t];
    u64t pr = pk(v, v * v);
    #pragma unroll
    for (int m = 16; m; m >>= 1) pr = add2(pr, shfl64x(pr, m));
    if (lane == 0) sw[w] = pr;
    __syncthreads();
    float s1 = 0.f, s2 = 0.f;
    #pragma unroll
    for (int i = 0; i < 8; i++) { float a, qq; upk(sw[i], a, qq); s1 += a; s2 += qq; }
    const float m = s1 * (1.0f / DD);
    const float var = s2 * (1.0f / DD) - m * m;
    g_pl[b * DD + t] = (v - m) * rsqrtf(var + 1e-5f) * gg[t] + bb[t];
}

// batched hidden GEMV: one warp per k-row computes ALL 32 batches (W1 read once).
__global__ void __launch_bounds__(256) ep_hidden_kernel(const float* __restrict__ W1,
                                                        const float* __restrict__ b1) {
    __shared__ float spl[BB * DD];
    const int tid = threadIdx.x, w = tid >> 5, lane = tid & 31;
    const int k = blockIdx.x * 8 + w;
    for (int i = tid; i < BB * DD; i += 256) spl[i] = g_pl[i];
    __syncthreads();
    const float4 w0 = *(const float4*)(W1 + (size_t)k * DD + 4 * lane);
    const float4 w1 = *(const float4*)(W1 + (size_t)k * DD + 128 + 4 * lane);
    float accv = 0.f;
    #pragma unroll
    for (int b = 0; b < BB; b++) {
        const float4 x0 = *(const float4*)(spl + b * DD + 4 * lane);
        const float4 x1 = *(const float4*)(spl + b * DD + 128 + 4 * lane);
        float s = w0.x * x0.x + w0.y * x0.y + w0.z * x0.z + w0.w * x0.w
                + w1.x * x1.x + w1.y * x1.y + w1.z * x1.z + w1.w * x1.w;
        #pragma unroll
        for (int m = 16; m; m >>= 1) s += __shfl_xor_sync(0xffffffffu, s, m);
        if (lane == b) accv = s;
    }
    const float hv = accv + b1[k];
    g_hid[(size_t)lane * 1024 + k] = 0.5f * hv * (1.0f + erff(hv * 0.70710678118654752f));
}

// batched mlp GEMV: warp per t-row, 8 batches per block, hid tiled through smem.
__global__ void __launch_bounds__(256) ep_mlp_kernel(const float* __restrict__ W2,
                                                     const float* __restrict__ b2) {
    __shared__ float shid[8 * DD];
    const int tid = threadIdx.x, w = tid >> 5, lane = tid & 31;
    const int t = (blockIdx.x >> 2) * 8 + w;
    const int b0 = (blockIdx.x & 3) * 8;
    float accv = 0.f;
    #pragma unroll 1
    for (int c = 0; c < 4; c++) {
        __syncthreads();
        for (int i = tid; i < 8 * DD; i += 256) {
            const int bl = i >> 8, d = i & 255;
            shid[i] = g_hid[(size_t)(b0 + bl) * 1024 + c * 256 + d];
        }
        __syncthreads();
        const float4 w0 = *(const float4*)(W2 + (size_t)t * 1024 + c * 256 + 4 * lane);
        const float4 w1 = *(const float4*)(W2 + (size_t)t * 1024 + c * 256 + 128 + 4 * lane);
        #pragma unroll
        for (int bl = 0; bl < 8; bl++) {
            const float4 x0 = *(const float4*)(shid + bl * DD + 4 * lane);
            const float4 x1 = *(const float4*)(shid + bl * DD + 128 + 4 * lane);
            float s = w0.x * x0.x + w0.y * x0.y + w0.z * x0.z + w0.w * x0.w
                    + w1.x * x1.x + w1.y * x1.y + w1.z * x1.z + w1.w * x1.w;
            #pragma unroll
            for (int m = 16; m; m >>= 1) s += __shfl_xor_sync(0xffffffffu, s, m);
            if (lane == bl) accv += s;
        }
    }
    if (lane < 8) {
        const int b = b0 + lane;
        g_res[b * DD + t] = accv + b2[t] + g_pl[b * DD + t];
    }
}

__global__ void ep_ln2_kernel(const float* __restrict__ gg, const float* __restrict__ bb,
                              float* __restrict__ out) {
    const int b = blockIdx.x, t = threadIdx.x, w = t >> 5, lane = t & 31;
    __shared__ u64t sw[8];
    const float v = g_res[b * DD + t];
    u64t pr = pk(v, v * v);
    #pragma unroll
    for (int m = 16; m; m >>= 1) pr = add2(pr, shfl64x(pr, m));
    if (lane == 0) sw[w] = pr;
    __syncthreads();
    float s1 = 0.f, s2 = 0.f;
    #pragma unroll
    for (int i = 0; i < 8; i++) { float a, qq; upk(sw[i], a, qq); s1 += a; s2 += qq; }
    const float m = s1 * (1.0f / DD);
    const float var = s2 * (1.0f / DD) - m * m;
    out[b * DD + t] = (v - m) * rsqrtf(var + 1e-5f) * gg[t] + bb[t];
}

// ------------------------- launch -------------------------
extern "C" void kernel_launch(void* const* d_in, const int* in_sizes, int n_in,
                              void* d_out, int out_size) {
    const float* tokens = (const float*)d_in[0];
    const void*  mask   = d_in[1];
    const float* query  = (const float*)d_in[2];
    const float* Wq     = (const float*)d_in[3];
    const float* bq     = (const float*)d_in[4];
    const float* Wk     = (const float*)d_in[5];
    const float* bk     = (const float*)d_in[6];
    const float* Wv     = (const float*)d_in[7];
    const float* bv     = (const float*)d_in[8];
    const float* Wo     = (const float*)d_in[9];
    const float* bo     = (const float*)d_in[10];
    const float* ln1g   = (const float*)d_in[11];
    const float* ln1b   = (const float*)d_in[12];
    const float* W1     = (const float*)d_in[13];
    const float* b1     = (const float*)d_in[14];
    const float* W2     = (const float*)d_in[15];
    const float* b2     = (const float*)d_in[16];
    const float* ln2g   = (const float*)d_in[17];
    const float* ln2b   = (const float*)d_in[18];
    float* out = (float*)d_out;

    prep_qh_kernel<<<32, 256>>>(query, Wq, bq, (const unsigned*)mask);
    prep_ws_kernel<<<8, 256>>>(Wk, bk);
    attn_main_kernel<<<dim3(64, 32), 128>>>(tokens, mask);
    ep_ctx_kernel<<<256, 256>>>(Wv, bv);
    ep_attnout_kernel<<<1024, 256>>>(Wo, bo);
    ep_ln1_kernel<<<32, 256>>>(ln1g, ln1b);
    ep_hidden_kernel<<<128, 256>>>(W1, b1);
    ep_mlp_kernel<<<128, 256>>>(W2, b2);
    ep_ln2_kernel<<<32, 256>>>(ln2g, ln2b, out);
}

// round 15
// speedup vs baseline: 1.2420x; 1.0559x over previous
#include <cuda_runtime.h>
#include <cuda_bf16.h>
#include <math.h>

#define BB 32
#define NN 8192
#define DD 256
#define HH 8
#define NSEG 64            // segments per batch (128 tokens each)
#define CHUNK_TOK 16
#define CHUNK_BYTES (CHUNK_TOK * DD * 4)   // 16 KB

typedef unsigned long long u64t;

// ------------------------- device scratch -------------------------
__device__ __align__(16) float g_Ws[HH * DD];               // prescaled by log2(e)
__device__ float g_c[HH];                                    // prescaled by log2(e)
__device__ __align__(16) float g_qh[DD];
__device__ __align__(16) float g_tpart[BB * NSEG * HH * DD]; // 16 MB
__device__ float g_zpart[BB * NSEG * HH];
__device__ __align__(16) float g_ctx[BB * DD];
__device__ __align__(16) float g_ao[BB * DD];
__device__ __align__(16) float g_pl[BB * DD];
__device__ __align__(16) float g_hid[BB * 4 * DD];
__device__ __align__(16) float g_res[BB * DD];
__device__ int g_mask_mode;

// ------------------------- f32x2 helpers -------------------------
__device__ __forceinline__ u64t pk(float lo, float hi) {
    u64t r; asm("mov.b64 %0,{%1,%2};" : "=l"(r) : "f"(lo), "f"(hi)); return r;
}
__device__ __forceinline__ void upk(u64t v, float& lo, float& hi) {
    asm("mov.b64 {%0,%1},%2;" : "=f"(lo), "=f"(hi) : "l"(v));
}
__device__ __forceinline__ u64t fma2(u64t a, u64t b, u64t c) {
    u64t d; asm("fma.rn.f32x2 %0,%1,%2,%3;" : "=l"(d) : "l"(a), "l"(b), "l"(c)); return d;
}
__device__ __forceinline__ u64t mul2(u64t a, u64t b) {
    u64t d; asm("mul.rn.f32x2 %0,%1,%2;" : "=l"(d) : "l"(a), "l"(b)); return d;
}
__device__ __forceinline__ u64t add2(u64t a, u64t b) {
    u64t d; asm("add.rn.f32x2 %0,%1,%2;" : "=l"(d) : "l"(a), "l"(b)); return d;
}
__device__ __forceinline__ float ex2f(float x) {
    float r; asm("ex2.approx.ftz.f32 %0,%1;" : "=f"(r) : "f"(x)); return r;
}
__device__ __forceinline__ u64t shfl64x(u64t v, int m) {
    return __shfl_xor_sync(0xffffffffu, v, m);
}

// ------------------------- mbarrier / bulk-async helpers -------------------------
__device__ __forceinline__ void mbar_init(unsigned mb, unsigned cnt) {
    asm volatile("mbarrier.init.shared.b64 [%0], %1;" :: "r"(mb), "r"(cnt) : "memory");
}
__device__ __forceinline__ void mbar_expect_tx(unsigned mb, unsigned bytes) {
    asm volatile("mbarrier.arrive.expect_tx.shared.b64 _, [%0], %1;" :: "r"(mb), "r"(bytes) : "memory");
}
__device__ __forceinline__ void bulk_cp(unsigned dst, const void* src, unsigned bytes, unsigned mb) {
    asm volatile("cp.async.bulk.shared::cta.global.mbarrier::complete_tx::bytes [%0], [%1], %2, [%3];"
                 :: "r"(dst), "l"(src), "r"(bytes), "r"(mb) : "memory");
}
__device__ __forceinline__ void mbar_wait(unsigned mb, unsigned par) {
    unsigned done;
    asm volatile("{\n\t.reg .pred p;\n\t"
                 "mbarrier.try_wait.parity.acquire.cta.shared::cta.b64 p, [%1], %2;\n\t"
                 "selp.b32 %0, 1, 0, p;\n\t}"
                 : "=r"(done) : "r"(mb), "r"(par) : "memory");
    while (!done) {
        asm volatile("{\n\t.reg .pred p;\n\t"
                     "mbarrier.try_wait.parity.acquire.cta.shared::cta.b64 p, [%1], %2, 0x989680;\n\t"
                     "selp.b32 %0, 1, 0, p;\n\t}"
                     : "=r"(done) : "r"(mb), "r"(par) : "memory");
    }
}

// ------------------------- mask handling -------------------------
__device__ __forceinline__ float load_maskv(const void* mask, int mode, size_t idx) {
    if (mode == 0) return ((const unsigned char*)mask)[idx] ? 1.0f : 0.0f;
    if (mode == 1) return ((const int*)mask)[idx] ? 1.0f : 0.0f;
    return ((const float*)mask)[idx];
}
__device__ __forceinline__ float mask_from_smem(const unsigned char* sm, int mode, int idx) {
    if (mode == 0) return sm[idx] ? 1.0f : 0.0f;
    if (mode == 1) return ((const int*)sm)[idx] ? 1.0f : 0.0f;
    return ((const float*)sm)[idx];
}

// ------------------------- warp dot helpers -------------------------
__device__ __forceinline__ float wdot256(const float* __restrict__ W,
                                         const float* __restrict__ x, int lane) {
    float4 w0 = *(const float4*)(W + 4 * lane);
    float4 w1 = *(const float4*)(W + 128 + 4 * lane);
    float4 x0 = *(const float4*)(x + 4 * lane);
    float4 x1 = *(const float4*)(x + 128 + 4 * lane);
    float s = w0.x * x0.x + w0.y * x0.y + w0.z * x0.z + w0.w * x0.w
            + w1.x * x1.x + w1.y * x1.y + w1.z * x1.z + w1.w * x1.w;
    #pragma unroll
    for (int m = 16; m; m >>= 1) s += __shfl_xor_sync(0xffffffffu, s, m);
    return s;
}

// ------------------------- prep: qh (+ mask detect in block 0) -------------------------
__global__ void prep_qh_kernel(const float* __restrict__ query, const float* __restrict__ Wq,
                               const float* __restrict__ bq, const unsigned* __restrict__ mask) {
    if (blockIdx.x == 0) {
        __shared__ int sF, sBig;
        const int tid = threadIdx.x;
        if (tid == 0) { sF = 0; sBig = 0; }
        __syncthreads();
        int f = 0, big = 0;
        for (int i = tid; i < 4096; i += blockDim.x) {
            unsigned x = mask[i];
            if (x == 0x3F800000u) f++;
            else if (x > 1u) big++;
        }
        atomicAdd(&sF, f); atomicAdd(&sBig, big);
        __syncthreads();
        if (tid == 0)
            g_mask_mode = (sF > 1000) ? 2 : ((sBig > 100) ? 0 : 1);
    }
    const int lane = threadIdx.x & 31;
    const int j = blockIdx.x * 8 + (threadIdx.x >> 5);
    float v = bq[j] + wdot256(Wq + (size_t)j * DD, query, lane);
    if (lane == 0) g_qh[j] = v * 0.17677669529663687f; // 1/sqrt(32)
}

// one block per head
__global__ void prep_ws_kernel(const float* __restrict__ Wk, const float* __restrict__ bk) {
    const int h = blockIdx.x, t = threadIdx.x;
    __shared__ float q[32];
    if (t < 32) q[t] = g_qh[h * 32 + t];
    __syncthreads();
    const float LOG2E = 1.4426950408889634f;
    float s = 0.f;
    #pragma unroll
    for (int dh = 0; dh < 32; dh++)
        s += q[dh] * Wk[(size_t)(h * 32 + dh) * DD + t];
    g_Ws[h * DD + t] = s * LOG2E;
    if (t == 0) {
        float c = 0.f;
        #pragma unroll
        for (int dh = 0; dh < 32; dh++) c += q[dh] * bk[h * 32 + dh];
        g_c[h] = c * LOG2E;
    }
}

// ------------------------- main fused attention pass: bulk-async smem pipeline ----------
// Grid (64 seg, 32 batch), 128 threads = 4 warps. Pair p = w>>1 owns 8 tokens per chunk;
// warp parity hh = w&1 owns heads hh*4..hh*4+3. Tokens AND masks staged to smem by
// cp.async.bulk (double-buffered 16-token chunks) — zero global loads in the hot loop.
__global__ void __launch_bounds__(128, 4) attn_main_kernel(const float* __restrict__ tokens,
                                                           const void* __restrict__ mask) {
    const int s = blockIdx.x, b = blockIdx.y;
    const int tid = threadIdx.x, w = tid >> 5, lane = tid & 31;
    const int p = w >> 1, hh = w & 1;

    __shared__ __align__(16) float sbuf[2][CHUNK_TOK * DD];   // 32 KB double buffer
    __shared__ __align__(16) unsigned char smask[2][64];      // staged mask bytes
    __shared__ __align__(8) unsigned long long smbar[2];
    __shared__ float szbf[16];
    u64t* sred = (u64t*)&sbuf[0][0];   // tail reuse (8 KB inside buffer 0)

    const unsigned sbase = (unsigned)__cvta_generic_to_shared(&sbuf[0][0]);
    const unsigned smk0  = (unsigned)__cvta_generic_to_shared(&smask[0][0]);
    const unsigned mb0 = (unsigned)__cvta_generic_to_shared(&smbar[0]);
    const unsigned mb1 = mb0 + 8;

    if (tid == 0) {
        mbar_init(mb0, 1);
        mbar_init(mb1, 1);
        asm volatile("fence.proxy.async.shared::cta;" ::: "memory");
    }
    __syncthreads();

    // Ws for my 4 heads, as f32x2 pairs
    u64t Ws2[4][4];
    #pragma unroll
    for (int hc = 0; hc < 4; hc++) {
        const int h = hh * 4 + hc;
        float4 a = *(const float4*)(g_Ws + h * DD + 4 * lane);
        float4 c = *(const float4*)(g_Ws + h * DD + 128 + 4 * lane);
        Ws2[hc][0] = pk(a.x, a.y);  Ws2[hc][1] = pk(a.z, a.w);
        Ws2[hc][2] = pk(c.x, c.y);  Ws2[hc][3] = pk(c.z, c.w);
    }
    const u64t cp0 = pk(g_c[hh * 4 + 0], g_c[hh * 4 + 1]);
    const u64t cp1 = pk(g_c[hh * 4 + 2], g_c[hh * 4 + 3]);

    u64t acc2[4][4];
    #pragma unroll
    for (int hc = 0; hc < 4; hc++)
        #pragma unroll
        for (int j = 0; j < 4; j++) acc2[hc][j] = 0ull;
    u64t zacc0 = 0ull, zacc1 = 0ull;

    const int mode = g_mask_mode;
    const unsigned msz = (mode == 0) ? 16u : 64u;             // mask bytes per 16 tokens
    const size_t blockbase = (size_t)b * NN + (size_t)s * 128; // token index
    const float* gsrc = tokens + blockbase * DD;
    const unsigned char* gmask = (const unsigned char*)mask +
                                 ((mode == 0) ? blockbase : blockbase * 4);
    const unsigned mstride = (mode == 0) ? CHUNK_TOK : CHUNK_TOK * 4;

    // issue chunk 0 (tokens + masks on the same barrier)
    if (tid == 0) {
        mbar_expect_tx(mb0, CHUNK_BYTES + msz);
        bulk_cp(sbase, gsrc, CHUNK_BYTES, mb0);
        bulk_cp(smk0, gmask, msz, mb0);
    }

    #pragma unroll 1
    for (int c = 0; c < 8; c++) {
        if (c > 0) __syncthreads();   // buffer (c+1)&1 free (chunk c-1 consumed)
        if (c < 7 && tid == 0) {
            const int nb = (c + 1) & 1;
            const unsigned mb = nb ? mb1 : mb0;
            mbar_expect_tx(mb, CHUNK_BYTES + msz);
            bulk_cp(sbase + nb * CHUNK_BYTES,
                    gsrc + (size_t)(c + 1) * CHUNK_TOK * DD, CHUNK_BYTES, mb);
            bulk_cp(smk0 + nb * 64, gmask + (size_t)(c + 1) * mstride, msz, mb);
        }
        mbar_wait((c & 1) ? mb1 : mb0, (c >> 1) & 1);

        const float* cbuf = &sbuf[c & 1][0];
        const unsigned char* cmsk = &smask[c & 1][0];
        #pragma unroll
        for (int gg = 0; gg < 2; gg++) {
            const int t0 = p * 8 + gg * 4;   // smem token index within chunk

            // masks from smem (bulk-staged, no global latency)
            float mv[4];
            #pragma unroll
            for (int it = 0; it < 4; it++)
                mv[it] = mask_from_smem(cmsk, mode, t0 + it);

            // score pass: transient LDS per token
            u64t bf[8];
            #pragma unroll
            for (int it = 0; it < 4; it++) {
                const float* tp = cbuf + (t0 + it) * DD;
                const float4 v0 = *(const float4*)(tp + 4 * lane);
                const float4 v1 = *(const float4*)(tp + 128 + 4 * lane);
                const u64t t0k = pk(v0.x, v0.y), t1k = pk(v0.z, v0.w);
                const u64t t2k = pk(v1.x, v1.y), t3k = pk(v1.z, v1.w);
                float sh[4];
                #pragma unroll
                for (int hc = 0; hc < 4; hc++) {
                    u64t pp = mul2(t0k, Ws2[hc][0]);
                    pp = fma2(t1k, Ws2[hc][1], pp);
                    pp = fma2(t2k, Ws2[hc][2], pp);
                    pp = fma2(t3k, Ws2[hc][3], pp);
                    float lo, hi; upk(pp, lo, hi);
                    sh[hc] = lo + hi;
                }
                bf[2 * it]     = pk(sh[0], sh[1]);
                bf[2 * it + 1] = pk(sh[2], sh[3]);
            }

            // butterfly: 8 independent chains, 5 levels
            #pragma unroll
            for (int m = 1; m <= 16; m <<= 1) {
                #pragma unroll
                for (int k = 0; k < 8; k++) bf[k] = add2(bf[k], shfl64x(bf[k], m));
            }

            // bias + exp2 + mask + z + accum (tk reloaded transiently)
            #pragma unroll
            for (int it = 0; it < 4; it++) {
                const u64t s0 = add2(bf[2 * it], cp0);
                const u64t s1 = add2(bf[2 * it + 1], cp1);
                float a0, a1, a2, a3;
                upk(s0, a0, a1); upk(s1, a2, a3);
                const float m4 = mv[it];
                const float e0 = ex2f(a0) * m4, e1 = ex2f(a1) * m4;
                const float e2 = ex2f(a2) * m4, e3 = ex2f(a3) * m4;
                zacc0 = add2(zacc0, pk(e0, e1));
                zacc1 = add2(zacc1, pk(e2, e3));
                const u64t eb0 = pk(e0, e0), eb1 = pk(e1, e1);
                const u64t eb2 = pk(e2, e2), eb3 = pk(e3, e3);
                const float* tp = cbuf + (t0 + it) * DD;
                const float4 v0 = *(const float4*)(tp + 4 * lane);
                const float4 v1 = *(const float4*)(tp + 128 + 4 * lane);
                const u64t t0k = pk(v0.x, v0.y), t1k = pk(v0.z, v0.w);
                const u64t t2k = pk(v1.x, v1.y), t3k = pk(v1.z, v1.w);
                acc2[0][0] = fma2(t0k, eb0, acc2[0][0]);
                acc2[0][1] = fma2(t1k, eb0, acc2[0][1]);
                acc2[0][2] = fma2(t2k, eb0, acc2[0][2]);
                acc2[0][3] = fma2(t3k, eb0, acc2[0][3]);
                acc2[1][0] = fma2(t0k, eb1, acc2[1][0]);
                acc2[1][1] = fma2(t1k, eb1, acc2[1][1]);
                acc2[1][2] = fma2(t2k, eb1, acc2[1][2]);
                acc2[1][3] = fma2(t3k, eb1, acc2[1][3]);
                acc2[2][0] = fma2(t0k, eb2, acc2[2][0]);
                acc2[2][1] = fma2(t1k, eb2, acc2[2][1]);
                acc2[2][2] = fma2(t2k, eb2, acc2[2][2]);
                acc2[2][3] = fma2(t3k, eb2, acc2[2][3]);
                acc2[3][0] = fma2(t0k, eb3, acc2[3][0]);
                acc2[3][1] = fma2(t1k, eb3, acc2[3][1]);
                acc2[3][2] = fma2(t2k, eb3, acc2[3][2]);
                acc2[3][3] = fma2(t3k, eb3, acc2[3][3]);
            }
        }
    }

    __syncthreads();   // all chunks consumed; safe to reuse sbuf as sred

    // ---- tail: combine the two stream-pairs ----
    #pragma unroll
    for (int phase = 0; phase < 2; phase++) {
        if (p == phase) {
            #pragma unroll
            for (int hc = 0; hc < 4; hc++) {
                #pragma unroll
                for (int j = 0; j < 4; j++) {
                    const int pairpos = (j < 2) ? (2 * lane + j) : (64 + 2 * lane + (j - 2));
                    const int idx = (hh * 4 + hc) * 128 + pairpos;
                    if (phase == 0) sred[idx] = acc2[hc][j];
                    else            sred[idx] = add2(sred[idx], acc2[hc][j]);
                }
            }
            if (lane == 0) {
                float z0, z1, z2, z3;
                upk(zacc0, z0, z1); upk(zacc1, z2, z3);
                szbf[w * 4 + 0] = z0; szbf[w * 4 + 1] = z1;
                szbf[w * 4 + 2] = z2; szbf[w * 4 + 3] = z3;
            }
        }
        __syncthreads();
    }

    const int part = b * NSEG + s;
    u64t* tpart2 = (u64t*)g_tpart;
    #pragma unroll
    for (int k = 0; k < 4; k++) {
        tpart2[(size_t)part * 1024 + k * 256 + tid]       = sred[k * 256 + tid];
        tpart2[(size_t)part * 1024 + k * 256 + 128 + tid] = sred[k * 256 + 128 + tid];
    }
    if (tid < 8) {
        const int hhb = tid >> 2, j = tid & 3;
        g_zpart[part * 8 + tid] = szbf[hhb * 4 + j] + szbf[8 + hhb * 4 + j];
    }
}

// ------------------------- fused ctx kernel: z + segment-reduce + Wv dots -------------------------
// Grid 256 = (batch, head); block 512 threads (8-way segment split for MLP).
__global__ void __launch_bounds__(512) ep_ctx_kernel(const float* __restrict__ Wv,
                                                     const float* __restrict__ bv) {
    const int b = blockIdx.x >> 3, h = blockIdx.x & 7;
    const int t = threadIdx.x, w = t >> 5, lane = t & 31;
    const int q = t & 63, r = t >> 6;   // r in 0..7
    __shared__ float4 sac[8][64];
    __shared__ float tbn[DD];
    __shared__ float szp[NSEG];
    __shared__ float zinv;

    const float4* base = (const float4*)(g_tpart) + (size_t)(b * NSEG) * 512 + h * 64;
    float4 acc = make_float4(0.f, 0.f, 0.f, 0.f);
    #pragma unroll
    for (int k = 0; k < 8; k++) {
        const float4 vv = base[(size_t)(r + 8 * k) * 512 + q];
        acc.x += vv.x; acc.y += vv.y; acc.z += vv.z; acc.w += vv.w;
    }
    sac[r][q] = acc;
    if (t < NSEG) szp[t] = g_zpart[(b * NSEG + t) * HH + h];
    __syncthreads();
    if (t == 0) {
        float z = 0.f;
        #pragma unroll
        for (int i = 0; i < NSEG; i++) z += szp[i];
        zinv = 1.0f / z;
    }
    __syncthreads();
    if (r == 0) {
        float4 sv = make_float4(0.f, 0.f, 0.f, 0.f);
        #pragma unroll
        for (int k = 0; k < 8; k++) {
            const float4 a = sac[k][q];
            sv.x += a.x; sv.y += a.y; sv.z += a.z; sv.w += a.w;
        }
        sv.x *= zinv; sv.y *= zinv; sv.z *= zinv; sv.w *= zinv;
        *(float4*)(tbn + 4 * q) = sv;
    }
    __syncthreads();

    // 32 ctx outputs for this head: 16 warps x 2
    #pragma unroll
    for (int o = 0; o < 2; o++) {
        const int j = h * 32 + w * 2 + o;
        float v = bv[j] + wdot256(Wv + (size_t)j * DD, tbn, lane);
        if (lane == 0) g_ctx[b * DD + j] = v;
    }
}

// ------------------------- epilogue -------------------------
__global__ void ep_attnout_kernel(const float* __restrict__ Wo, const float* __restrict__ bo) {
    const int lane = threadIdx.x & 31;
    const int gw = blockIdx.x * 8 + (threadIdx.x >> 5);
    const int b = gw & 31, t = gw >> 5;
    float v = bo[t] + wdot256(Wo + (size_t)t * DD, g_ctx + (size_t)b * DD, lane);
    if (lane == 0) g_ao[b * DD + t] = v;
}

__global__ void ep_ln1_kernel(const float* __restrict__ gg, const float* __restrict__ bb) {
    const int b = blockIdx.x, t = threadIdx.x, w = t >> 5, lane = t & 31;
    __shared__ u64t sw[8];
    const float v = g_ao[b * DD + t];
    u64t pr = pk(v, v * v);
    #pragma unroll
    for (int m = 16; m; m >>= 1) pr = add2(pr, shfl64x(pr, m));
    if (lane == 0) sw[w] = pr;
    __syncthreads();
    float s1 = 0.f, s2 = 0.f;
    #pragma unroll
    for (int i = 0; i < 8; i++) { float a, qq; upk(sw[i], a, qq); s1 += a; s2 += qq; }
    const float m = s1 * (1.0f / DD);
    const float var = s2 * (1.0f / DD) - m * m;
    g_pl[b * DD + t] = (v - m) * rsqrtf(var + 1e-5f) * gg[t] + bb[t];
}

// batched hidden GEMV: one warp per k-row computes ALL 32 batches (W1 read once).
__global__ void __launch_bounds__(256) ep_hidden_kernel(const float* __restrict__ W1,
                                                        const float* __restrict__ b1) {
    __shared__ float spl[BB * DD];
    const int tid = threadIdx.x, w = tid >> 5, lane = tid & 31;
    const int k = blockIdx.x * 8 + w;
    for (int i = tid; i < BB * DD; i += 256) spl[i] = g_pl[i];
    __syncthreads();
    const float4 w0 = *(const float4*)(W1 + (size_t)k * DD + 4 * lane);
    const float4 w1 = *(const float4*)(W1 + (size_t)k * DD + 128 + 4 * lane);
    float accv = 0.f;
    #pragma unroll
    for (int b = 0; b < BB; b++) {
        const float4 x0 = *(const float4*)(spl + b * DD + 4 * lane);
        const float4 x1 = *(const float4*)(spl + b * DD + 128 + 4 * lane);
        float s = w0.x * x0.x + w0.y * x0.y + w0.z * x0.z + w0.w * x0.w
                + w1.x * x1.x + w1.y * x1.y + w1.z * x1.z + w1.w * x1.w;
        #pragma unroll
        for (int m = 16; m; m >>= 1) s += __shfl_xor_sync(0xffffffffu, s, m);
        if (lane == b) accv = s;
    }
    const float hv = accv + b1[k];
    g_hid[(size_t)lane * 1024 + k] = 0.5f * hv * (1.0f + erff(hv * 0.70710678118654752f));
}

// batched mlp GEMV: warp per t-row, 8 batches per block, hid tiled through smem.
__global__ void __launch_bounds__(256) ep_mlp_kernel(const float* __restrict__ W2,
                                                     const float* __restrict__ b2) {
    __shared__ float shid[8 * DD];
    const int tid = threadIdx.x, w = tid >> 5, lane = tid & 31;
    const int t = (blockIdx.x >> 2) * 8 + w;
    const int b0 = (blockIdx.x & 3) * 8;
    float accv = 0.f;
    #pragma unroll 1
    for (int c = 0; c < 4; c++) {
        __syncthreads();
        for (int i = tid; i < 8 * DD; i += 256) {
            const int bl = i >> 8, d = i & 255;
            shid[i] = g_hid[(size_t)(b0 + bl) * 1024 + c * 256 + d];
        }
        __syncthreads();
        const float4 w0 = *(const float4*)(W2 + (size_t)t * 1024 + c * 256 + 4 * lane);
        const float4 w1 = *(const float4*)(W2 + (size_t)t * 1024 + c * 256 + 128 + 4 * lane);
        #pragma unroll
        for (int bl = 0; bl < 8; bl++) {
            const float4 x0 = *(const float4*)(shid + bl * DD + 4 * lane);
            const float4 x1 = *(const float4*)(shid + bl * DD + 128 + 4 * lane);
            float s = w0.x * x0.x + w0.y * x0.y + w0.z * x0.z + w0.w * x0.w
                    + w1.x * x1.x + w1.y * x1.y + w1.z * x1.z + w1.w * x1.w;
            #pragma unroll
            for (int m = 16; m; m >>= 1) s += __shfl_xor_sync(0xffffffffu, s, m);
            if (lane == bl) accv += s;
        }
    }
    if (lane < 8) {
        const int b = b0 + lane;
        g_res[b * DD + t] = accv + b2[t] + g_pl[b * DD + t];
    }
}

__global__ void ep_ln2_kernel(const float* __restrict__ gg, const float* __restrict__ bb,
                              float* __restrict__ out) {
    const int b = blockIdx.x, t = threadIdx.x, w = t >> 5, lane = t & 31;
    __shared__ u64t sw[8];
    const float v = g_res[b * DD + t];
    u64t pr = pk(v, v * v);
    #pragma unroll
    for (int m = 16; m; m >>= 1) pr = add2(pr, shfl64x(pr, m));
    if (lane == 0) sw[w] = pr;
    __syncthreads();
    float s1 = 0.f, s2 = 0.f;
    #pragma unroll
    for (int i = 0; i < 8; i++) { float a, qq; upk(sw[i], a, qq); s1 += a; s2 += qq; }
    const float m = s1 * (1.0f / DD);
    const float var = s2 * (1.0f / DD) - m * m;
    out[b * DD + t] = (v - m) * rsqrtf(var + 1e-5f) * gg[t] + bb[t];
}

// ------------------------- launch -------------------------
extern "C" void kernel_launch(void* const* d_in, const int* in_sizes, int n_in,
                              void* d_out, int out_size) {
    const float* tokens = (const float*)d_in[0];
    const void*  mask   = d_in[1];
    const float* query  = (const float*)d_in[2];
    const float* Wq     = (const float*)d_in[3];
    const float* bq     = (const float*)d_in[4];
    const float* Wk     = (const float*)d_in[5];
    const float* bk     = (const float*)d_in[6];
    const float* Wv     = (const float*)d_in[7];
    const float* bv     = (const float*)d_in[8];
    const float* Wo     = (const float*)d_in[9];
    const float* bo     = (const float*)d_in[10];
    const float* ln1g   = (const float*)d_in[11];
    const float* ln1b   = (const float*)d_in[12];
    const float* W1     = (const float*)d_in[13];
    const float* b1     = (const float*)d_in[14];
    const float* W2     = (const float*)d_in[15];
    const float* b2     = (const float*)d_in[16];
    const float* ln2g   = (const float*)d_in[17];
    const float* ln2b   = (const float*)d_in[18];
    float* out = (float*)d_out;

    prep_qh_kernel<<<32, 256>>>(query, Wq, bq, (const unsigned*)mask);
    prep_ws_kernel<<<8, 256>>>(Wk, bk);
    attn_main_kernel<<<dim3(64, 32), 128>>>(tokens, mask);
    ep_ctx_kernel<<<256, 512>>>(Wv, bv);
    ep_attnout_kernel<<<1024, 256>>>(Wo, bo);
    ep_ln1_kernel<<<32, 256>>>(ln1g, ln1b);
    ep_hidden_kernel<<<128, 256>>>(W1, b1);
    ep_mlp_kernel<<<128, 256>>>(W2, b2);
    ep_ln2_kernel<<<32, 256>>>(ln2g, ln2b, out);
}